// round 13
// baseline (speedup 1.0000x reference)
#include <cuda_runtime.h>

namespace {

constexpr int RAD   = 7;          // N = 2*ceil(2.5)+1 = 7
constexpr int TBX   = 32;         // threads x
constexpr int TBY   = 4;          // threads y
constexpr int PXY   = 4;          // pixels per thread in y
constexpr int TILEY = TBY * PXY;  // 16 output rows per block
constexpr int SW    = TBX + 2*RAD;    // 46
constexpr int SH    = TILEY + 2*RAD;  // 30
constexpr int IMH   = 1080;
constexpr int IMW   = 1920;
constexpr int CH    = 11;

#define EPSF  1e-4f
#define FCAP  14426.950408889634f          /* 1e4 * log2e */
#define NC2   -0.72134752044448f           /* -0.5*log2e  */

// NINVD_L2E[k] = -log2(e)/sqrt(k); k=0 sentinel -1e30: invdz*(-1e30) -> -huge
// -> fmax(., -FCAP) = -FCAP, matching reference den = max(dz*0, eps) = eps
// (zd = 0 at dsi = 0 anyway).
__device__ constexpr float NINVD_L2E[99] = {
    -1e30f,       -1.44269504f, -1.02014424f, -0.83293944f, -0.72134752f,
    -0.64519935f, -0.58898486f, -0.54529656f, -0.51007212f, -0.48089835f,
    -0.45621984f, -0.43498237f, -0.41646972f, -0.40012747f, -0.38556183f,
    -0.37247373f, -0.36067376f, -0.34990480f, -0.34009409f, -0.33102480f,
    -0.32259967f, -0.31482513f, -0.30758643f, -0.30082509f, -0.29449243f,
    -0.28853901f, -0.28293539f, -0.27764648f, -0.27264828f, -0.26790684f,
    -0.26340594f, -0.25912240f, -0.25503606f, -0.25114328f, -0.24742265f,
    -0.24386200f, -0.24044918f, -0.23717857f, -0.23403768f, -0.23101807f,
    -0.22810992f, -0.22531137f, -0.22261272f, -0.22000923f, -0.21749119f,
    -0.21506125f, -0.21271045f, -0.21043517f, -0.20823486f, -0.20609929f,
    -0.20403378f, -0.20202950f, -0.20008659f, -0.19819969f, -0.19636738f,
    -0.19458680f, -0.19284900f, -0.19115746f, -0.18950668f, -0.18789521f,
    -0.18633688f, -0.18480333f, -0.18331146f, -0.18184540f, -0.18041844f,
    -0.17902041f, -0.17766033f, -0.17632993f, -0.17501816f, -0.17374384f,
    -0.17248900f, -0.17126993f, -0.17004704f, -0.16888040f, -0.16773528f,
    -0.16659174f, -0.16549221f, -0.16440389f, -0.16334410f, -0.16231653f,
    -0.16129984f, -0.16029945f, -0.15932285f, -0.15835942f, -0.15741374f,
    -0.15648424f, -0.15557203f, -0.15467385f, -0.15379850f, -0.15293093f,
    -0.15207893f, -0.15123993f, -0.15041596f, -0.14960526f, -0.14880778f,
    -0.14801817f, -0.14724766f, -0.14648368f, -0.14574043f
};

__device__ __forceinline__ float ex2f_(float x) {
    float y; asm("ex2.approx.f32 %0, %1;" : "=f"(y) : "f"(x)); return y;
}
__device__ __forceinline__ float lg2f_(float x) {
    float y; asm("lg2.approx.f32 %0, %1;" : "=f"(y) : "f"(x)); return y;
}
__device__ __forceinline__ float rcpf_(float x) {
    float y; asm("rcp.approx.f32 %0, %1;" : "=f"(y) : "f"(x)); return y;
}

// ---- packed f32x2 helpers (sm_103a) — ACCUMULATORS ONLY ----
typedef unsigned long long u64;
__device__ __forceinline__ u64 pack2_(float lo, float hi) {
    u64 d; asm("mov.b64 %0, {%1, %2};" : "=l"(d) : "f"(lo), "f"(hi)); return d;
}
__device__ __forceinline__ void unpack2_(float& lo, float& hi, u64 v) {
    asm("mov.b64 {%0, %1}, %2;" : "=f"(lo), "=f"(hi) : "l"(v));
}
__device__ __forceinline__ u64 fma2_(u64 a, u64 b, u64 c) {
    u64 d; asm("fma.rn.f32x2 %0, %1, %2, %3;" : "=l"(d) : "l"(a), "l"(b), "l"(c));
    return d;
}
__device__ __forceinline__ u64 add2_(u64 a, u64 b) {
    u64 d; asm("add.rn.f32x2 %0, %1, %2;" : "=l"(d) : "l"(a), "l"(b)); return d;
}

// Scalar per-pixel weight, R10-proven form. dsi compile-time after unroll.
// w = ex2( 128*lg2(sat(dot)) + |zd| * max(invdz*(-c), -FCAP) + NC2*dsi )
// sat(dot)<=0 -> lg2 = -inf -> w = 0 (matches reference eps^128 underflow).
__device__ __forceinline__ float wpix_(bool act, const float4 nz,
                                       float Nx, float Ny, float Nz,
                                       float Zc, float invdz, int dsi)
{
    if (!act) return 0.0f;
    float dot = __saturatef(fmaf(nz.x, Nx, fmaf(nz.y, Ny, nz.z * Nz)));
    float lt  = lg2f_(dot);
    float nfp = fmaxf(invdz * NINVD_L2E[dsi], -FCAP);   // FMNMX on alu
    float zd  = nz.w - Zc;
    return ex2f_(fmaf(lt, 128.0f, fmaf(fabsf(zd), nfp, NC2 * (float)dsi)));
}

} // namespace

__global__ void __launch_bounds__(TBX*TBY, 5)
BilateralDenoiser_44427141710593_kernel(const float* __restrict__ in,
                                        float* __restrict__ out)
{
    __shared__ float4 s_nz[SH * SW];   // (nrm.x, nrm.y, nrm.z, z)
    __shared__ float4 s_cd[SH * SW];   // (col.r, col.g, col.b, dz)

    const int bx  = blockIdx.x * TBX;
    const int by  = blockIdx.y * TILEY;
    const int tid = threadIdx.y * TBX + threadIdx.x;

    // Cooperative halo load; OOB -> zeros => dot=0 -> w=0 (matches reference).
    #pragma unroll
    for (int i = tid; i < SH * SW; i += TBX * TBY) {
        const int ly = i / SW;
        const int lx = i - ly * SW;
        const int gy = by + ly - RAD;
        const int gx = bx + lx - RAD;
        float4 nz = make_float4(0.f, 0.f, 0.f, 0.f);
        float4 cd = make_float4(0.f, 0.f, 0.f, 0.f);
        if ((unsigned)gy < (unsigned)IMH && (unsigned)gx < (unsigned)IMW) {
            const float* p = in + ((size_t)gy * IMW + gx) * CH;
            cd.x = p[0]; cd.y = p[1]; cd.z = p[2];      // col
            nz.x = p[3]; nz.y = p[4]; nz.z = p[5];      // nrm
            nz.w = p[9];                                 // z
            cd.w = p[10];                                // dz
        }
        s_nz[i] = nz;
        s_cd[i] = cd;
    }
    __syncthreads();

    const int c0 = (threadIdx.y * PXY + RAD) * SW + (threadIdx.x + RAD);
    const float4* __restrict__ snz = s_nz + c0;
    const float4* __restrict__ scd = s_cd + c0;

    // Per-pixel center constants (4 pixels, scalar — no input packing).
    float Nx[PXY], Ny[PXY], Nz[PXY], Zc[PXY], ivd[PXY];
    #pragma unroll
    for (int p = 0; p < PXY; ++p) {
        const float4 n = snz[p * SW];
        Nx[p] = n.x; Ny[p] = n.y; Nz[p] = n.z; Zc[p] = n.w;
        ivd[p] = rcpf_(fmaxf(scd[p * SW].w, 0.0f));
    }

    // Packed accumulators: pair A = pixels (0,1), pair B = pixels (2,3).
    u64 arA = 0ull, agA = 0ull, abA = 0ull, awA = 0ull;
    u64 arB = 0ull, agB = 0ull, abB = 0ull, awB = 0ull;

    // One smem load per (dy,dx) feeds up to 4 pixels (offsets dy..dy-3).
    #pragma unroll
    for (int dy = -RAD; dy <= RAD + PXY - 1; ++dy) {
        #pragma unroll
        for (int dx = -RAD; dx <= RAD; ++dx) {
            const float4 nz = snz[dy*SW + dx];
            const float4 cd = scd[dy*SW + dx];

            const bool a0 = (dy-0 >= -RAD) && (dy-0 <= RAD);   // compile-time
            const bool a1 = (dy-1 >= -RAD) && (dy-1 <= RAD);
            const bool a2 = (dy-2 >= -RAD) && (dy-2 <= RAD);
            const bool a3 = (dy-3 >= -RAD) && (dy-3 <= RAD);

            if (a0 | a1) {
                const float w0 = wpix_(a0, nz, Nx[0], Ny[0], Nz[0], Zc[0],
                                       ivd[0], (dy-0)*(dy-0) + dx*dx);
                const float w1 = wpix_(a1, nz, Nx[1], Ny[1], Nz[1], Zc[1],
                                       ivd[1], (dy-1)*(dy-1) + dx*dx);
                const u64 w01 = pack2_(w0, w1);
                arA = fma2_(pack2_(cd.x, cd.x), w01, arA);
                agA = fma2_(pack2_(cd.y, cd.y), w01, agA);
                abA = fma2_(pack2_(cd.z, cd.z), w01, abA);
                awA = add2_(awA, w01);
            }
            if (a2 | a3) {
                const float w2 = wpix_(a2, nz, Nx[2], Ny[2], Nz[2], Zc[2],
                                       ivd[2], (dy-2)*(dy-2) + dx*dx);
                const float w3 = wpix_(a3, nz, Nx[3], Ny[3], Nz[3], Zc[3],
                                       ivd[3], (dy-3)*(dy-3) + dx*dx);
                const u64 w23 = pack2_(w2, w3);
                arB = fma2_(pack2_(cd.x, cd.x), w23, arB);
                agB = fma2_(pack2_(cd.y, cd.y), w23, agB);
                abB = fma2_(pack2_(cd.z, cd.z), w23, abB);
                awB = add2_(awB, w23);
            }
        }
    }

    float ar[PXY], ag[PXY], ab[PXY], aw[PXY];
    unpack2_(ar[0], ar[1], arA); unpack2_(ar[2], ar[3], arB);
    unpack2_(ag[0], ag[1], agA); unpack2_(ag[2], ag[3], agB);
    unpack2_(ab[0], ab[1], abA); unpack2_(ab[2], ab[3], abB);
    unpack2_(aw[0], aw[1], awA); unpack2_(aw[2], aw[3], awB);

    const int gx  = bx + threadIdx.x;
    const int gy0 = by + threadIdx.y * PXY;
    #pragma unroll
    for (int p = 0; p < PXY; ++p) {
        const int gy = gy0 + p;
        if (gy < IMH) {                              // partial last y-block
            const float inv = 1.0f / fmaxf(aw[p], EPSF);
            float* o = out + ((size_t)gy * IMW + gx) * 3;
            o[0] = ar[p] * inv; o[1] = ag[p] * inv; o[2] = ab[p] * inv;
        }
    }
}

extern "C" void kernel_launch(void* const* d_in, const int* in_sizes, int n_in,
                              void* d_out, int out_size)
{
    const float* in = (const float*)d_in[0];
    float* out = (float*)d_out;
    dim3 block(TBX, TBY);
    dim3 grid(IMW / TBX, (IMH + TILEY - 1) / TILEY);   // 60 x 68
    BilateralDenoiser_44427141710593_kernel<<<grid, block>>>(in, out);
}

// round 14
// speedup vs baseline: 1.3855x; 1.3855x over previous
#include <cuda_runtime.h>

namespace {

constexpr int RAD   = 7;          // N = 2*ceil(2.5)+1 = 7
constexpr int TBX   = 32;         // threads x
constexpr int TBY   = 6;          // threads y
constexpr int PXY   = 2;          // pixels per thread in y
constexpr int TILEY = TBY * PXY;  // 12 output rows per block (1080/12 = 90)
constexpr int SW    = TBX + 2*RAD;    // 46
constexpr int SH    = TILEY + 2*RAD;  // 26
constexpr int IMH   = 1080;
constexpr int IMW   = 1920;
constexpr int CH    = 11;

#define EPSF   1e-4f
#define C_L2E  1.4426950408889634f         /* log2(e)      */
#define NC2    -0.72134752044448f          /* -0.5*log2(e) */

// C_TAB[k] = log2(e)/sqrt(k), k>=1 (k=0 is special-cased out).
__device__ constexpr float C_TAB[99] = {
    0.0f,         1.44269504f, 1.02014424f, 0.83293944f, 0.72134752f,
    0.64519935f,  0.58898486f, 0.54529656f, 0.51007212f, 0.48089835f,
    0.45621984f,  0.43498237f, 0.41646972f, 0.40012747f, 0.38556183f,
    0.37247373f,  0.36067376f, 0.34990480f, 0.34009409f, 0.33102480f,
    0.32259967f,  0.31482513f, 0.30758643f, 0.30082509f, 0.29449243f,
    0.28853901f,  0.28293539f, 0.27764648f, 0.27264828f, 0.26790684f,
    0.26340594f,  0.25912240f, 0.25503606f, 0.25114328f, 0.24742265f,
    0.24386200f,  0.24044918f, 0.23717857f, 0.23403768f, 0.23101807f,
    0.22810992f,  0.22531137f, 0.22261272f, 0.22000923f, 0.21749119f,
    0.21506125f,  0.21271045f, 0.21043517f, 0.20823486f, 0.20609929f,
    0.20403378f,  0.20202950f, 0.20008659f, 0.19819969f, 0.19636738f,
    0.19458680f,  0.19284900f, 0.19115746f, 0.18950668f, 0.18789521f,
    0.18633688f,  0.18480333f, 0.18331146f, 0.18184540f, 0.18041844f,
    0.17902041f,  0.17766033f, 0.17632993f, 0.17501816f, 0.17374384f,
    0.17248900f,  0.17126993f, 0.17004704f, 0.16888040f, 0.16773528f,
    0.16659174f,  0.16549221f, 0.16440389f, 0.16334410f, 0.16231653f,
    0.16129984f,  0.16029945f, 0.15932285f, 0.15835942f, 0.15741374f,
    0.15648424f,  0.15557203f, 0.15467385f, 0.15379850f, 0.15293093f,
    0.15207893f,  0.15123993f, 0.15041596f, 0.14960526f, 0.14880778f,
    0.14801817f,  0.14724766f, 0.14648368f, 0.14574043f
};

__device__ __forceinline__ float ex2f_(float x) {
    float y; asm("ex2.approx.f32 %0, %1;" : "=f"(y) : "f"(x)); return y;
}
__device__ __forceinline__ float lg2f_(float x) {
    float y; asm("lg2.approx.f32 %0, %1;" : "=f"(y) : "f"(x)); return y;
}
__device__ __forceinline__ float rcpf_(float x) {
    float y; asm("rcp.approx.f32 %0, %1;" : "=f"(y) : "f"(x)); return y;
}

// ---- packed f32x2 helpers (sm_103a) — ACCUMULATORS ONLY ----
typedef unsigned long long u64;
__device__ __forceinline__ u64 pack2_(float lo, float hi) {
    u64 d; asm("mov.b64 %0, {%1, %2};" : "=l"(d) : "f"(lo), "f"(hi)); return d;
}
__device__ __forceinline__ void unpack2_(float& lo, float& hi, u64 v) {
    asm("mov.b64 {%0, %1}, %2;" : "=f"(lo), "=f"(hi) : "l"(v));
}
__device__ __forceinline__ u64 fma2_(u64 a, u64 b, u64 c) {
    u64 d; asm("fma.rn.f32x2 %0, %1, %2, %3;" : "=l"(d) : "l"(a), "l"(b), "l"(c));
    return d;
}

// Per-pixel weight. dsi compile-time. Depth term uses per-pixel affine form:
// s = zt*A + nB == A*(zt - Zc);  A = min(1/max(dz,0), 1e4), nB = -Zc*A.
// Normal pixels (A<1e4): m*log2e = |s| * log2e/dist  (exact — product can
// never exceed the 1e4 cap since A<=1e4, 1/dist<=1).
// Capped pixels (A==1e4, i.e. dz<=~1e-4): factor := 1e4 (exact for dz<=0;
// approximate only in the measure-~3e-5 window dz in (1e-4/dist, 1e-4)).
// dsi==0: zd==0 in the reference -> depth term is exactly 1; skip it.
__device__ __forceinline__ float wpix_(bool act, const float4 nz,
                                       float Nx, float Ny, float Nz,
                                       float A, float nB, bool cap, int dsi)
{
    if (!act) return 0.0f;
    float dot = __saturatef(fmaf(nz.x, Nx, fmaf(nz.y, Ny, nz.z * Nz)));
    float lt  = lg2f_(dot);
    if (dsi == 0) return ex2f_(lt * 128.0f);
    float s   = fmaf(nz.w, A, nB);
    float Cv  = cap ? C_L2E : C_TAB[dsi];              // FSEL (alu)
    float q   = fmaf(-fabsf(s), Cv, NC2 * (float)dsi); // ctap immediate
    return ex2f_(fmaf(lt, 128.0f, q));
}

} // namespace

__global__ void __launch_bounds__(TBX*TBY, 5)
BilateralDenoiser_44427141710593_kernel(const float* __restrict__ in,
                                        float* __restrict__ out)
{
    __shared__ float4 s_nz[SH * SW];   // (nrm.x, nrm.y, nrm.z, z)
    __shared__ float4 s_cd[SH * SW];   // (col.r, col.g, col.b, 1.0f)

    const int bx  = blockIdx.x * TBX;
    const int by  = blockIdx.y * TILEY;
    const int tid = threadIdx.y * TBX + threadIdx.x;

    // Cooperative halo load; OOB -> zeros => dot=0 -> w=0 (matches reference).
    // cd.w is set to 1.0f so (cd.z, cd.w) forms a ready (b, 1) fma2 operand.
    #pragma unroll
    for (int i = tid; i < SH * SW; i += TBX * TBY) {
        const int ly = i / SW;
        const int lx = i - ly * SW;
        const int gy = by + ly - RAD;
        const int gx = bx + lx - RAD;
        float4 nz = make_float4(0.f, 0.f, 0.f, 0.f);
        float4 cd = make_float4(0.f, 0.f, 0.f, 1.0f);
        if ((unsigned)gy < (unsigned)IMH && (unsigned)gx < (unsigned)IMW) {
            const float* p = in + ((size_t)gy * IMW + gx) * CH;
            cd.x = p[0]; cd.y = p[1]; cd.z = p[2];      // col
            nz.x = p[3]; nz.y = p[4]; nz.z = p[5];      // nrm
            nz.w = p[9];                                 // z
        }
        s_nz[i] = nz;
        s_cd[i] = cd;
    }
    __syncthreads();

    const int c0 = (threadIdx.y * PXY + RAD) * SW + (threadIdx.x + RAD);
    const float4* __restrict__ snz = s_nz + c0;
    const float4* __restrict__ scd = s_cd + c0;

    const int gx  = bx + threadIdx.x;
    const int gy0 = by + threadIdx.y * PXY;

    // Per-pixel center constants; dz read straight from gmem (L2-hot).
    float Nx[PXY], Ny[PXY], Nz[PXY], A[PXY], nB[PXY];
    bool  cap[PXY];
    #pragma unroll
    for (int p = 0; p < PXY; ++p) {
        const float4 n = snz[p * SW];
        Nx[p] = n.x; Ny[p] = n.y; Nz[p] = n.z;
        const float dzv = in[((size_t)(gy0 + p) * IMW + gx) * CH + 10];
        A[p]   = fminf(rcpf_(fmaxf(dzv, 0.0f)), 1e4f);
        cap[p] = (A[p] == 1e4f);
        nB[p]  = -n.w * A[p];
    }

    // Packed accumulators per pixel: (r,g) and (b,w).
    u64 rg0 = 0ull, bw0 = 0ull, rg1 = 0ull, bw1 = 0ull;

    // One smem load per (dy,dx) feeds pixel0's tap (dy) and pixel1's (dy-1).
    #pragma unroll
    for (int dy = -RAD; dy <= RAD + 1; ++dy) {
        #pragma unroll
        for (int dx = -RAD; dx <= RAD; ++dx) {
            const float4 nz = snz[dy*SW + dx];
            const float4 cd = scd[dy*SW + dx];

            const bool a0 = (dy <= RAD);                // compile-time
            const bool a1 = (dy >= -RAD + 1);           // compile-time

            const float w0 = wpix_(a0, nz, Nx[0], Ny[0], Nz[0],
                                   A[0], nB[0], cap[0], dy*dy + dx*dx);
            const float w1 = wpix_(a1, nz, Nx[1], Ny[1], Nz[1],
                                   A[1], nB[1], cap[1], (dy-1)*(dy-1) + dx*dx);

            // (cd.x,cd.y) and (cd.z,1.0f) are aligned LDS.128 register pairs.
            u64 cdrg, cdb1;
            {
                float2 t0 = make_float2(cd.x, cd.y);
                float2 t1 = make_float2(cd.z, cd.w);   // cd.w == 1.0f
                cdrg = *reinterpret_cast<u64*>(&t0);
                cdb1 = *reinterpret_cast<u64*>(&t1);
            }
            if (a0) {
                const u64 w00 = pack2_(w0, w0);
                rg0 = fma2_(cdrg, w00, rg0);
                bw0 = fma2_(cdb1, w00, bw0);
            }
            if (a1) {
                const u64 w11 = pack2_(w1, w1);
                rg1 = fma2_(cdrg, w11, rg1);
                bw1 = fma2_(cdb1, w11, bw1);
            }
        }
    }

    float r0,g0,b0,aw0, r1,g1,b1,aw1;
    unpack2_(r0, g0, rg0); unpack2_(b0, aw0, bw0);
    unpack2_(r1, g1, rg1); unpack2_(b1, aw1, bw1);

    {
        const float inv = 1.0f / fmaxf(aw0, EPSF);
        float* o = out + ((size_t)gy0 * IMW + gx) * 3;
        o[0] = r0 * inv; o[1] = g0 * inv; o[2] = b0 * inv;
    }
    {
        const float inv = 1.0f / fmaxf(aw1, EPSF);
        float* o = out + ((size_t)(gy0 + 1) * IMW + gx) * 3;
        o[0] = r1 * inv; o[1] = g1 * inv; o[2] = b1 * inv;
    }
}

extern "C" void kernel_launch(void* const* d_in, const int* in_sizes, int n_in,
                              void* d_out, int out_size)
{
    const float* in = (const float*)d_in[0];
    float* out = (float*)d_out;
    dim3 block(TBX, TBY);
    dim3 grid(IMW / TBX, IMH / TILEY);   // 60 x 90, exact tiling
    BilateralDenoiser_44427141710593_kernel<<<grid, block>>>(in, out);
}

// round 15
// speedup vs baseline: 1.5380x; 1.1101x over previous
#include <cuda_runtime.h>

namespace {

constexpr int RAD   = 7;          // N = 2*ceil(2.5)+1 = 7
constexpr int RMAX2 = 49;         // circular tap mask: keep dsi <= 49
constexpr int TBX   = 32;         // threads x
constexpr int TBY   = 6;          // threads y
constexpr int PXY   = 2;          // pixels per thread in y
constexpr int TILEY = TBY * PXY;  // 12 output rows per block (1080/12 = 90)
constexpr int SW    = TBX + 2*RAD;    // 46
constexpr int SH    = TILEY + 2*RAD;  // 26
constexpr int IMH   = 1080;
constexpr int IMW   = 1920;
constexpr int CH    = 11;

#define EPSF   1e-4f
#define C_L2E  1.4426950408889634f         /* log2(e)      */
#define NC2    -0.72134752044448f          /* -0.5*log2(e) */

// C_TAB[k] = log2(e)/sqrt(k), k>=1 (k=0 special-cased; k<=49 used).
__device__ constexpr float C_TAB[50] = {
    0.0f,         1.44269504f, 1.02014424f, 0.83293944f, 0.72134752f,
    0.64519935f,  0.58898486f, 0.54529656f, 0.51007212f, 0.48089835f,
    0.45621984f,  0.43498237f, 0.41646972f, 0.40012747f, 0.38556183f,
    0.37247373f,  0.36067376f, 0.34990480f, 0.34009409f, 0.33102480f,
    0.32259967f,  0.31482513f, 0.30758643f, 0.30082509f, 0.29449243f,
    0.28853901f,  0.28293539f, 0.27764648f, 0.27264828f, 0.26790684f,
    0.26340594f,  0.25912240f, 0.25503606f, 0.25114328f, 0.24742265f,
    0.24386200f,  0.24044918f, 0.23717857f, 0.23403768f, 0.23101807f,
    0.22810992f,  0.22531137f, 0.22261272f, 0.22000923f, 0.21749119f,
    0.21506125f,  0.21271045f, 0.21043517f, 0.20823486f, 0.20609929f
};

__device__ __forceinline__ float ex2f_(float x) {
    float y; asm("ex2.approx.f32 %0, %1;" : "=f"(y) : "f"(x)); return y;
}
__device__ __forceinline__ float lg2f_(float x) {
    float y; asm("lg2.approx.f32 %0, %1;" : "=f"(y) : "f"(x)); return y;
}
__device__ __forceinline__ float rcpf_(float x) {
    float y; asm("rcp.approx.f32 %0, %1;" : "=f"(y) : "f"(x)); return y;
}

// ---- packed f32x2 helpers (sm_103a) — register packs only, NO address-taken
// locals (R14's reinterpret-through-stack caused STL/LDL traffic).
typedef unsigned long long u64;
__device__ __forceinline__ u64 pack2_(float lo, float hi) {
    u64 d; asm("mov.b64 %0, {%1, %2};" : "=l"(d) : "f"(lo), "f"(hi)); return d;
}
__device__ __forceinline__ void unpack2_(float& lo, float& hi, u64 v) {
    asm("mov.b64 {%0, %1}, %2;" : "=f"(lo), "=f"(hi) : "l"(v));
}
__device__ __forceinline__ u64 fma2_(u64 a, u64 b, u64 c) {
    u64 d; asm("fma.rn.f32x2 %0, %1, %2, %3;" : "=l"(d) : "l"(a), "l"(b), "l"(c));
    return d;
}

// Per-pixel weight. dsi compile-time after unroll.
// Depth term in per-pixel affine form: s = zt*A + nB == A*(zt - Zc), where
// A = min(1/max(dz,0), 1e4), nB = -Zc*A. Normal pixels (A<1e4): exact.
// Capped pixels (dz<=~1e-4): factor := 1e4 (exact for dz<=0; approximate only
// in the measure-~3e-5 window). dsi==0: zd==0 -> depth term exactly 1.
// sat(dot)<=0 -> lg2=-inf -> w=0 (matches reference eps^128 fp32 underflow).
__device__ __forceinline__ float wpix_(const float4 nz,
                                       float Nx, float Ny, float Nz,
                                       float A, float nB, bool cap, int dsi)
{
    float dot = __saturatef(fmaf(nz.x, Nx, fmaf(nz.y, Ny, nz.z * Nz)));
    float lt  = lg2f_(dot);
    if (dsi == 0) return ex2f_(lt * 128.0f);
    float s   = fmaf(nz.w, A, nB);
    float Cv  = cap ? C_L2E : C_TAB[dsi];              // FSEL (alu)
    float q   = fmaf(-fabsf(s), Cv, NC2 * (float)dsi); // ctap immediate
    return ex2f_(fmaf(lt, 128.0f, q));
}

} // namespace

__global__ void __launch_bounds__(TBX*TBY, 5)
BilateralDenoiser_44427141710593_kernel(const float* __restrict__ in,
                                        float* __restrict__ out)
{
    __shared__ float4 s_nz[SH * SW];   // (nrm.x, nrm.y, nrm.z, z)
    __shared__ float4 s_cd[SH * SW];   // (col.r, col.g, col.b, 1.0f)

    const int bx  = blockIdx.x * TBX;
    const int by  = blockIdx.y * TILEY;
    const int tid = threadIdx.y * TBX + threadIdx.x;

    // Cooperative halo load; OOB -> zeros => dot=0 -> w=0 (matches reference).
    #pragma unroll
    for (int i = tid; i < SH * SW; i += TBX * TBY) {
        const int ly = i / SW;
        const int lx = i - ly * SW;
        const int gy = by + ly - RAD;
        const int gx = bx + lx - RAD;
        float4 nz = make_float4(0.f, 0.f, 0.f, 0.f);
        float4 cd = make_float4(0.f, 0.f, 0.f, 1.0f);
        if ((unsigned)gy < (unsigned)IMH && (unsigned)gx < (unsigned)IMW) {
            const float* p = in + ((size_t)gy * IMW + gx) * CH;
            cd.x = p[0]; cd.y = p[1]; cd.z = p[2];      // col
            nz.x = p[3]; nz.y = p[4]; nz.z = p[5];      // nrm
            nz.w = p[9];                                 // z
        }
        s_nz[i] = nz;
        s_cd[i] = cd;
    }
    __syncthreads();

    const int c0 = (threadIdx.y * PXY + RAD) * SW + (threadIdx.x + RAD);
    const float4* __restrict__ snz = s_nz + c0;
    const float4* __restrict__ scd = s_cd + c0;

    const int gx  = bx + threadIdx.x;
    const int gy0 = by + threadIdx.y * PXY;

    // Per-pixel center constants; dz read straight from gmem (L2-hot).
    float Nx[PXY], Ny[PXY], Nz[PXY], A[PXY], nB[PXY];
    bool  cap[PXY];
    #pragma unroll
    for (int p = 0; p < PXY; ++p) {
        const float4 n = snz[p * SW];
        Nx[p] = n.x; Ny[p] = n.y; Nz[p] = n.z;
        const float dzv = in[((size_t)(gy0 + p) * IMW + gx) * CH + 10];
        A[p]   = fminf(rcpf_(fmaxf(dzv, 0.0f)), 1e4f);
        cap[p] = (A[p] == 1e4f);
        nB[p]  = -n.w * A[p];
    }

    // Packed accumulators per pixel: (r,g) and (b,w).
    u64 rg0 = 0ull, bw0 = 0ull, rg1 = 0ull, bw1 = 0ull;

    // One smem load per active (dy,dx). Circular mask dsi<=49 drops taps with
    // w_xy <= e^-25 ~ 1.4e-11 (other factors only shrink w further) — far
    // below the 1e-3 aggregate error budget. Mask is compile-time, so fully
    // inactive positions drop their LDS too.
    #pragma unroll
    for (int dy = -RAD; dy <= RAD + 1; ++dy) {
        #pragma unroll
        for (int dx = -RAD; dx <= RAD; ++dx) {
            const int dsi0 = dy*dy + dx*dx;
            const int dsi1 = (dy-1)*(dy-1) + dx*dx;
            const bool a0 = (dy <= RAD)      && (dsi0 <= RMAX2);  // compile-time
            const bool a1 = (dy >= -RAD + 1) && (dsi1 <= RMAX2);  // compile-time
            if (!(a0 | a1)) continue;

            const float4 nz = snz[dy*SW + dx];
            const float4 cd = scd[dy*SW + dx];

            // Register packs (mov.b64) — never through memory.
            const u64 cdrg = pack2_(cd.x, cd.y);
            const u64 cdb1 = pack2_(cd.z, cd.w);       // cd.w == 1.0f

            if (a0) {
                const float w0 = wpix_(nz, Nx[0], Ny[0], Nz[0],
                                       A[0], nB[0], cap[0], dsi0);
                const u64 w00 = pack2_(w0, w0);
                rg0 = fma2_(cdrg, w00, rg0);
                bw0 = fma2_(cdb1, w00, bw0);
            }
            if (a1) {
                const float w1 = wpix_(nz, Nx[1], Ny[1], Nz[1],
                                       A[1], nB[1], cap[1], dsi1);
                const u64 w11 = pack2_(w1, w1);
                rg1 = fma2_(cdrg, w11, rg1);
                bw1 = fma2_(cdb1, w11, bw1);
            }
        }
    }

    float r0,g0,b0,aw0, r1,g1,b1,aw1;
    unpack2_(r0, g0, rg0); unpack2_(b0, aw0, bw0);
    unpack2_(r1, g1, rg1); unpack2_(b1, aw1, bw1);

    {
        const float inv = 1.0f / fmaxf(aw0, EPSF);
        float* o = out + ((size_t)gy0 * IMW + gx) * 3;
        o[0] = r0 * inv; o[1] = g0 * inv; o[2] = b0 * inv;
    }
    {
        const float inv = 1.0f / fmaxf(aw1, EPSF);
        float* o = out + ((size_t)(gy0 + 1) * IMW + gx) * 3;
        o[0] = r1 * inv; o[1] = g1 * inv; o[2] = b1 * inv;
    }
}

extern "C" void kernel_launch(void* const* d_in, const int* in_sizes, int n_in,
                              void* d_out, int out_size)
{
    const float* in = (const float*)d_in[0];
    float* out = (float*)d_out;
    dim3 block(TBX, TBY);
    dim3 grid(IMW / TBX, IMH / TILEY);   // 60 x 90, exact tiling
    BilateralDenoiser_44427141710593_kernel<<<grid, block>>>(in, out);
}

// round 16
// speedup vs baseline: 1.5495x; 1.0075x over previous
#include <cuda_runtime.h>

namespace {

constexpr int RAD   = 7;          // N = 2*ceil(2.5)+1 = 7
constexpr int RMAX2 = 49;         // circular tap mask: keep dsi <= 49
constexpr int TBX   = 32;         // threads x
constexpr int TBY   = 6;          // threads y
constexpr int PXY   = 2;          // pixels per thread in y
constexpr int TILEY = TBY * PXY;  // 12 output rows per block (1080/12 = 90)
constexpr int SW    = TBX + 2*RAD;    // 46
constexpr int SH    = TILEY + 2*RAD;  // 26
constexpr int IMH   = 1080;
constexpr int IMW   = 1920;
constexpr int CH    = 11;

#define EPSF   1e-4f
#define C_L2E  1.4426950408889634f         /* log2(e)      */
#define NC2    -0.72134752044448f          /* -0.5*log2(e) */

// C_TAB[k] = log2(e)/sqrt(k), k>=1 (k=0 special-cased; k<=49 used).
__device__ constexpr float C_TAB[50] = {
    0.0f,         1.44269504f, 1.02014424f, 0.83293944f, 0.72134752f,
    0.64519935f,  0.58898486f, 0.54529656f, 0.51007212f, 0.48089835f,
    0.45621984f,  0.43498237f, 0.41646972f, 0.40012747f, 0.38556183f,
    0.37247373f,  0.36067376f, 0.34990480f, 0.34009409f, 0.33102480f,
    0.32259967f,  0.31482513f, 0.30758643f, 0.30082509f, 0.29449243f,
    0.28853901f,  0.28293539f, 0.27764648f, 0.27264828f, 0.26790684f,
    0.26340594f,  0.25912240f, 0.25503606f, 0.25114328f, 0.24742265f,
    0.24386200f,  0.24044918f, 0.23717857f, 0.23403768f, 0.23101807f,
    0.22810992f,  0.22531137f, 0.22261272f, 0.22000923f, 0.21749119f,
    0.21506125f,  0.21271045f, 0.21043517f, 0.20823486f, 0.20609929f
};

__device__ __forceinline__ float ex2f_(float x) {
    float y; asm("ex2.approx.f32 %0, %1;" : "=f"(y) : "f"(x)); return y;
}
__device__ __forceinline__ float lg2f_(float x) {
    float y; asm("lg2.approx.f32 %0, %1;" : "=f"(y) : "f"(x)); return y;
}
__device__ __forceinline__ float rcpf_(float x) {
    float y; asm("rcp.approx.f32 %0, %1;" : "=f"(y) : "f"(x)); return y;
}

// ---- packed f32x2 helpers (sm_103a) — register packs only, never through
// memory (address-taken locals spill to stack -> STL/LDL, R14 lesson).
typedef unsigned long long u64;
__device__ __forceinline__ u64 pack2_(float lo, float hi) {
    u64 d; asm("mov.b64 %0, {%1, %2};" : "=l"(d) : "f"(lo), "f"(hi)); return d;
}
__device__ __forceinline__ void unpack2_(float& lo, float& hi, u64 v) {
    asm("mov.b64 {%0, %1}, %2;" : "=f"(lo), "=f"(hi) : "l"(v));
}
__device__ __forceinline__ u64 fma2_(u64 a, u64 b, u64 c) {
    u64 d; asm("fma.rn.f32x2 %0, %1, %2, %3;" : "=l"(d) : "l"(a), "l"(b), "l"(c));
    return d;
}

// Per-pixel weight. dsi compile-time after unroll.
// Depth term in per-pixel affine form: s = zt*A + nB == A*(zt - Zc), where
// A = min(1/max(dz,0), 1e4), nB = -Zc*A. Normal pixels (A<1e4): exact.
// Capped pixels (dz<=~1e-4): factor := 1e4 (exact for dz<=0; approximate only
// in the measure-~3e-5 window). dsi==0: zd==0 -> depth term exactly 1.
// sat(dot)<=0 -> lg2=-inf -> w=0 (matches reference eps^128 fp32 underflow).
__device__ __forceinline__ float wpix_(const float4 nz,
                                       float Nx, float Ny, float Nz,
                                       float A, float nB, bool cap, int dsi)
{
    float dot = __saturatef(fmaf(nz.x, Nx, fmaf(nz.y, Ny, nz.z * Nz)));
    float lt  = lg2f_(dot);
    if (dsi == 0) return ex2f_(lt * 128.0f);
    float s   = fmaf(nz.w, A, nB);
    float Cv  = cap ? C_L2E : C_TAB[dsi];              // FSEL (alu)
    float q   = fmaf(-fabsf(s), Cv, NC2 * (float)dsi); // ctap immediate
    return ex2f_(fmaf(lt, 128.0f, q));
}

} // namespace

__global__ void __launch_bounds__(TBX*TBY, 5)
BilateralDenoiser_44427141710593_kernel(const float* __restrict__ in,
                                        float* __restrict__ out)
{
    __shared__ float4 s_nz[SH * SW];   // (nrm.x, nrm.y, nrm.z, z)
    __shared__ float4 s_cd[SH * SW];   // (col.r, col.g) | (col.b, 1.0f)

    const int bx  = blockIdx.x * TBX;
    const int by  = blockIdx.y * TILEY;
    const int tid = threadIdx.y * TBX + threadIdx.x;

    // Cooperative halo load; OOB -> zeros => dot=0 -> w=0 (matches reference).
    #pragma unroll
    for (int i = tid; i < SH * SW; i += TBX * TBY) {
        const int ly = i / SW;
        const int lx = i - ly * SW;
        const int gy = by + ly - RAD;
        const int gx = bx + lx - RAD;
        float4 nz = make_float4(0.f, 0.f, 0.f, 0.f);
        float4 cd = make_float4(0.f, 0.f, 0.f, 1.0f);
        if ((unsigned)gy < (unsigned)IMH && (unsigned)gx < (unsigned)IMW) {
            const float* p = in + ((size_t)gy * IMW + gx) * CH;
            cd.x = p[0]; cd.y = p[1]; cd.z = p[2];      // col
            nz.x = p[3]; nz.y = p[4]; nz.z = p[5];      // nrm
            nz.w = p[9];                                 // z
        }
        s_nz[i] = nz;
        s_cd[i] = cd;
    }
    __syncthreads();

    const int c0 = (threadIdx.y * PXY + RAD) * SW + (threadIdx.x + RAD);
    const float4* __restrict__ snz = s_nz + c0;
    // u64 view of the cd tile: element 2*i = (r,g), 2*i+1 = (b,1.0f).
    // Direct LDS.64 loads give fma2-ready aligned register pairs with NO MOVs.
    const u64* __restrict__ scd64 = reinterpret_cast<const u64*>(s_cd + c0);

    const int gx  = bx + threadIdx.x;
    const int gy0 = by + threadIdx.y * PXY;

    // Per-pixel center constants; dz read straight from gmem (L2-hot).
    float Nx[PXY], Ny[PXY], Nz[PXY], A[PXY], nB[PXY];
    bool  cap[PXY];
    #pragma unroll
    for (int p = 0; p < PXY; ++p) {
        const float4 n = snz[p * SW];
        Nx[p] = n.x; Ny[p] = n.y; Nz[p] = n.z;
        const float dzv = in[((size_t)(gy0 + p) * IMW + gx) * CH + 10];
        A[p]   = fminf(rcpf_(fmaxf(dzv, 0.0f)), 1e4f);
        cap[p] = (A[p] == 1e4f);
        nB[p]  = -n.w * A[p];
    }

    // Packed accumulators per pixel: (r,g) and (b,w).
    u64 rg0 = 0ull, bw0 = 0ull, rg1 = 0ull, bw1 = 0ull;

    // One smem load set per active (dy,dx). Circular mask dsi<=49 drops taps
    // with w_xy <= e^-25 ~ 1.4e-11; even with the 1/eps weight-floor
    // amplification that is ~2e-7 relative — far inside the 1e-3 budget.
    #pragma unroll
    for (int dy = -RAD; dy <= RAD + 1; ++dy) {
        #pragma unroll
        for (int dx = -RAD; dx <= RAD; ++dx) {
            const int dsi0 = dy*dy + dx*dx;
            const int dsi1 = (dy-1)*(dy-1) + dx*dx;
            const bool a0 = (dy <= RAD)      && (dsi0 <= RMAX2);  // compile-time
            const bool a1 = (dy >= -RAD + 1) && (dsi1 <= RMAX2);  // compile-time
            if (!(a0 | a1)) continue;

            const float4 nz = snz[dy*SW + dx];
            const u64 cdrg = scd64[(dy*SW + dx) * 2 + 0];   // LDS.64 (r,g)
            const u64 cdb1 = scd64[(dy*SW + dx) * 2 + 1];   // LDS.64 (b,1)

            if (a0) {
                const float w0 = wpix_(nz, Nx[0], Ny[0], Nz[0],
                                       A[0], nB[0], cap[0], dsi0);
                const u64 w00 = pack2_(w0, w0);
                rg0 = fma2_(cdrg, w00, rg0);
                bw0 = fma2_(cdb1, w00, bw0);
            }
            if (a1) {
                const float w1 = wpix_(nz, Nx[1], Ny[1], Nz[1],
                                       A[1], nB[1], cap[1], dsi1);
                const u64 w11 = pack2_(w1, w1);
                rg1 = fma2_(cdrg, w11, rg1);
                bw1 = fma2_(cdb1, w11, bw1);
            }
        }
    }

    float r0,g0,b0,aw0, r1,g1,b1,aw1;
    unpack2_(r0, g0, rg0); unpack2_(b0, aw0, bw0);
    unpack2_(r1, g1, rg1); unpack2_(b1, aw1, bw1);

    {
        const float inv = 1.0f / fmaxf(aw0, EPSF);
        float* o = out + ((size_t)gy0 * IMW + gx) * 3;
        o[0] = r0 * inv; o[1] = g0 * inv; o[2] = b0 * inv;
    }
    {
        const float inv = 1.0f / fmaxf(aw1, EPSF);
        float* o = out + ((size_t)(gy0 + 1) * IMW + gx) * 3;
        o[0] = r1 * inv; o[1] = g1 * inv; o[2] = b1 * inv;
    }
}

extern "C" void kernel_launch(void* const* d_in, const int* in_sizes, int n_in,
                              void* d_out, int out_size)
{
    const float* in = (const float*)d_in[0];
    float* out = (float*)d_out;
    dim3 block(TBX, TBY);
    dim3 grid(IMW / TBX, IMH / TILEY);   // 60 x 90, exact tiling
    BilateralDenoiser_44427141710593_kernel<<<grid, block>>>(in, out);
}

// round 17
// speedup vs baseline: 1.7780x; 1.1475x over previous
#include <cuda_runtime.h>

namespace {

constexpr int RAD   = 7;          // N = 2*ceil(2.5)+1 = 7
constexpr int RMAX2 = 49;         // circular tap mask: keep dsi <= 49
constexpr int TBX   = 32;         // threads x
constexpr int TBY   = 8;          // threads y
constexpr int PXY   = 2;          // pixels per thread in y
constexpr int TILEY = TBY * PXY;  // 16 output rows per block
constexpr int SW    = TBX + 2*RAD;    // 46
constexpr int SH    = TILEY + 2*RAD;  // 30
constexpr int IMH   = 1080;
constexpr int IMW   = 1920;
constexpr int CH    = 11;

#define EPSF   1e-4f
#define C_L2E  1.4426950408889634f         /* log2(e)      */
#define NC2    -0.72134752044448f          /* -0.5*log2(e) */

// C_TAB[k] = log2(e)/sqrt(k), k>=1 (k=0 special-cased; k<=49 used).
__device__ constexpr float C_TAB[50] = {
    0.0f,         1.44269504f, 1.02014424f, 0.83293944f, 0.72134752f,
    0.64519935f,  0.58898486f, 0.54529656f, 0.51007212f, 0.48089835f,
    0.45621984f,  0.43498237f, 0.41646972f, 0.40012747f, 0.38556183f,
    0.37247373f,  0.36067376f, 0.34990480f, 0.34009409f, 0.33102480f,
    0.32259967f,  0.31482513f, 0.30758643f, 0.30082509f, 0.29449243f,
    0.28853901f,  0.28293539f, 0.27764648f, 0.27264828f, 0.26790684f,
    0.26340594f,  0.25912240f, 0.25503606f, 0.25114328f, 0.24742265f,
    0.24386200f,  0.24044918f, 0.23717857f, 0.23403768f, 0.23101807f,
    0.22810992f,  0.22531137f, 0.22261272f, 0.22000923f, 0.21749119f,
    0.21506125f,  0.21271045f, 0.21043517f, 0.20823486f, 0.20609929f
};

__device__ __forceinline__ float ex2f_(float x) {
    float y; asm("ex2.approx.f32 %0, %1;" : "=f"(y) : "f"(x)); return y;
}
__device__ __forceinline__ float lg2f_(float x) {
    float y; asm("lg2.approx.f32 %0, %1;" : "=f"(y) : "f"(x)); return y;
}
__device__ __forceinline__ float rcpf_(float x) {
    float y; asm("rcp.approx.f32 %0, %1;" : "=f"(y) : "f"(x)); return y;
}

// ---- packed f32x2 helpers (sm_103a) — register packs only, never through
// memory (address-taken locals spill to stack -> STL/LDL, R14 lesson).
typedef unsigned long long u64;
__device__ __forceinline__ u64 pack2_(float lo, float hi) {
    u64 d; asm("mov.b64 %0, {%1, %2};" : "=l"(d) : "f"(lo), "f"(hi)); return d;
}
__device__ __forceinline__ void unpack2_(float& lo, float& hi, u64 v) {
    asm("mov.b64 {%0, %1}, %2;" : "=f"(lo), "=f"(hi) : "l"(v));
}
__device__ __forceinline__ u64 fma2_(u64 a, u64 b, u64 c) {
    u64 d; asm("fma.rn.f32x2 %0, %1, %2, %3;" : "=l"(d) : "l"(a), "l"(b), "l"(c));
    return d;
}

// Per-pixel weight. dsi compile-time after unroll.
// Depth term in per-pixel affine form: s = zt*A + nB == A*(zt - Zc), where
// A = min(1/max(dz,0), 1e4), nB = -Zc*A. Normal pixels (A<1e4): exact.
// Capped pixels (dz<=~1e-4): factor := 1e4 (exact for dz<=0; approximate only
// in the measure-~3e-5 window). dsi==0: zd==0 -> depth term exactly 1.
// sat(dot)<=0 -> lg2=-inf -> w=0 (matches reference eps^128 fp32 underflow).
__device__ __forceinline__ float wpix_(const float4 nz,
                                       float Nx, float Ny, float Nz,
                                       float A, float nB, bool cap, int dsi)
{
    float dot = __saturatef(fmaf(nz.x, Nx, fmaf(nz.y, Ny, nz.z * Nz)));
    float lt  = lg2f_(dot);
    if (dsi == 0) return ex2f_(lt * 128.0f);
    float s   = fmaf(nz.w, A, nB);
    float Cv  = cap ? C_L2E : C_TAB[dsi];              // FSEL (alu)
    float q   = fmaf(-fabsf(s), Cv, NC2 * (float)dsi); // ctap immediate
    return ex2f_(fmaf(lt, 128.0f, q));
}

} // namespace

__global__ void __launch_bounds__(TBX*TBY, 4)
BilateralDenoiser_44427141710593_kernel(const float* __restrict__ in,
                                        float* __restrict__ out)
{
    __shared__ float4 s_nz[SH * SW];   // (nrm.x, nrm.y, nrm.z, z)
    __shared__ float4 s_cd[SH * SW];   // (col.r, col.g) | (col.b, 1.0f)

    const int bx  = blockIdx.x * TBX;
    const int by  = blockIdx.y * TILEY;
    const int tid = threadIdx.y * TBX + threadIdx.x;

    // Cooperative halo load; OOB -> zeros => dot=0 -> w=0 (matches reference).
    #pragma unroll
    for (int i = tid; i < SH * SW; i += TBX * TBY) {
        const int ly = i / SW;
        const int lx = i - ly * SW;
        const int gy = by + ly - RAD;
        const int gx = bx + lx - RAD;
        float4 nz = make_float4(0.f, 0.f, 0.f, 0.f);
        float4 cd = make_float4(0.f, 0.f, 0.f, 1.0f);
        if ((unsigned)gy < (unsigned)IMH && (unsigned)gx < (unsigned)IMW) {
            const float* p = in + ((size_t)gy * IMW + gx) * CH;
            cd.x = p[0]; cd.y = p[1]; cd.z = p[2];      // col
            nz.x = p[3]; nz.y = p[4]; nz.z = p[5];      // nrm
            nz.w = p[9];                                 // z
        }
        s_nz[i] = nz;
        s_cd[i] = cd;
    }
    __syncthreads();

    const int c0 = (threadIdx.y * PXY + RAD) * SW + (threadIdx.x + RAD);
    const float4* __restrict__ snz = s_nz + c0;
    // u64 view of the cd tile: element 2*i = (r,g), 2*i+1 = (b,1.0f).
    // Direct LDS.64 loads give fma2-ready aligned register pairs.
    const u64* __restrict__ scd64 = reinterpret_cast<const u64*>(s_cd + c0);

    const int gx  = bx + threadIdx.x;
    const int gy0 = by + threadIdx.y * PXY;

    // Per-pixel center constants; dz read straight from gmem (L2-hot).
    // gy0+p can exceed IMH-1 only in the last y-block; clamp the gmem read
    // (result unused there — store is guarded).
    float Nx[PXY], Ny[PXY], Nz[PXY], A[PXY], nB[PXY];
    bool  cap[PXY];
    #pragma unroll
    for (int p = 0; p < PXY; ++p) {
        const float4 n = snz[p * SW];
        Nx[p] = n.x; Ny[p] = n.y; Nz[p] = n.z;
        const int gyc = min(gy0 + p, IMH - 1);
        const float dzv = in[((size_t)gyc * IMW + gx) * CH + 10];
        A[p]   = fminf(rcpf_(fmaxf(dzv, 0.0f)), 1e4f);
        cap[p] = (A[p] == 1e4f);
        nB[p]  = -n.w * A[p];
    }

    // Packed accumulators per pixel: (r,g) and (b,w).
    u64 rg0 = 0ull, bw0 = 0ull, rg1 = 0ull, bw1 = 0ull;

    // One smem load set per active (dy,dx). Circular mask dsi<=49 drops taps
    // with w_xy <= e^-25 ~ 1.4e-11; even with the 1/eps weight-floor
    // amplification that is ~2e-7 relative — far inside the 1e-3 budget.
    #pragma unroll
    for (int dy = -RAD; dy <= RAD + 1; ++dy) {
        #pragma unroll
        for (int dx = -RAD; dx <= RAD; ++dx) {
            const int dsi0 = dy*dy + dx*dx;
            const int dsi1 = (dy-1)*(dy-1) + dx*dx;
            const bool a0 = (dy <= RAD)      && (dsi0 <= RMAX2);  // compile-time
            const bool a1 = (dy >= -RAD + 1) && (dsi1 <= RMAX2);  // compile-time
            if (!(a0 | a1)) continue;

            const float4 nz = snz[dy*SW + dx];
            const u64 cdrg = scd64[(dy*SW + dx) * 2 + 0];   // LDS.64 (r,g)
            const u64 cdb1 = scd64[(dy*SW + dx) * 2 + 1];   // LDS.64 (b,1)

            if (a0) {
                const float w0 = wpix_(nz, Nx[0], Ny[0], Nz[0],
                                       A[0], nB[0], cap[0], dsi0);
                const u64 w00 = pack2_(w0, w0);
                rg0 = fma2_(cdrg, w00, rg0);
                bw0 = fma2_(cdb1, w00, bw0);
            }
            if (a1) {
                const float w1 = wpix_(nz, Nx[1], Ny[1], Nz[1],
                                       A[1], nB[1], cap[1], dsi1);
                const u64 w11 = pack2_(w1, w1);
                rg1 = fma2_(cdrg, w11, rg1);
                bw1 = fma2_(cdb1, w11, bw1);
            }
        }
    }

    float r0,g0,b0,aw0, r1,g1,b1,aw1;
    unpack2_(r0, g0, rg0); unpack2_(b0, aw0, bw0);
    unpack2_(r1, g1, rg1); unpack2_(b1, aw1, bw1);

    if (gy0 < IMH) {
        const float inv = 1.0f / fmaxf(aw0, EPSF);
        float* o = out + ((size_t)gy0 * IMW + gx) * 3;
        o[0] = r0 * inv; o[1] = g0 * inv; o[2] = b0 * inv;
    }
    if (gy0 + 1 < IMH) {
        const float inv = 1.0f / fmaxf(aw1, EPSF);
        float* o = out + ((size_t)(gy0 + 1) * IMW + gx) * 3;
        o[0] = r1 * inv; o[1] = g1 * inv; o[2] = b1 * inv;
    }
}

extern "C" void kernel_launch(void* const* d_in, const int* in_sizes, int n_in,
                              void* d_out, int out_size)
{
    const float* in = (const float*)d_in[0];
    float* out = (float*)d_out;
    dim3 block(TBX, TBY);
    dim3 grid(IMW / TBX, (IMH + TILEY - 1) / TILEY);   // 60 x 68
    BilateralDenoiser_44427141710593_kernel<<<grid, block>>>(in, out);
}